// round 6
// baseline (speedup 1.0000x reference)
#include <cuda_runtime.h>
#include <math.h>

// ---------------- problem constants ------------------------------------------
#define NMAX   100000
#define EMAX   3200000
#define ETOTMAX (EMAX + NMAX)
#define HC     32          // H*C

// ---------------- scratch (device globals: allocation-free rule) -------------
__device__ __align__(128) float g_xl [NMAX * HC];
__device__ __align__(128) float g_xr [NMAX * HC];
__device__ __align__(128) float g_h  [NMAX * HC];
__device__ __align__(128) int   g_src[ETOTMAX];
__device__ __align__(128) int   g_dst[ETOTMAX];
__device__ __align__(128) int   g_csrc[ETOTMAX];   // CSR: src ids sorted by dst
__device__ __align__(128) int   g_cnt[NMAX];
__device__ __align__(128) int   g_rp [NMAX + 1];   // CSR row pointers
__device__ __align__(128) int   g_pos[NMAX];       // scatter cursors
__device__ int g_i32flag;   // 1 if edge_index delivered as int32, 0 if int64

// ---------------- small PTX helpers ------------------------------------------
__device__ __forceinline__ unsigned long long dup2(float v) {
    unsigned long long r;
    asm("mov.b64 %0, {%1, %1};" : "=l"(r) : "f"(v));
    return r;
}
__device__ __forceinline__ float2 unpack2(unsigned long long v) {
    float2 r;
    asm("mov.b64 {%0, %1}, %2;" : "=f"(r.x), "=f"(r.y) : "l"(v));
    return r;
}
#define FMA2(d, a, b) asm("fma.rn.f32x2 %0, %1, %2, %0;" : "+l"(d) : "l"(a), "l"(b))

// ---------------- init: zero histogram + reset dtype flag ---------------------
__global__ void k_init0(int n) {
    int i = blockIdx.x * blockDim.x + threadIdx.x;
    if (i < n) g_cnt[i] = 0;
    if (i == 0) g_i32flag = 0;
}

__global__ void k_detect(const int* __restrict__ w, int E) {
    long long i = (long long)blockIdx.x * blockDim.x + threadIdx.x;
    if (i >= E) return;
    if (w[2 * i + 1] != 0) g_i32flag = 1;     // benign race
}

// ---------------- edge decode + histogram (fused) ------------------------------
__global__ void k_prep_hist(const void* __restrict__ eiv, int E, int n) {
    int i = blockIdx.x * blockDim.x + threadIdx.x;
    int etot = E + n;
    if (i >= etot) return;
    int s, d;
    if (i < E) {
        if (g_i32flag) {
            const int* ei = (const int*)eiv;
            s = ei[i]; d = ei[(size_t)E + i];
        } else {
            const long long* ei = (const long long*)eiv;
            s = (int)ei[i]; d = (int)ei[(size_t)E + i];
        }
        s = min(max(s, 0), n - 1);
        d = min(max(d, 0), n - 1);
    } else {
        s = i - E; d = i - E;
    }
    g_src[i] = s;
    g_dst[i] = d;
    atomicAdd(&g_cnt[d], 1);
}

// ---------------- scan + scatter (counting sort by dst) ------------------------
__device__ __align__(128) int g_blk[128];
__global__ __launch_bounds__(1024) void k_scan1(int n) {
    __shared__ int sh[1024];
    int i = blockIdx.x * 1024 + threadIdx.x;
    int v = (i < n) ? g_cnt[i] : 0;
    sh[threadIdx.x] = v;
    __syncthreads();
#pragma unroll
    for (int o = 1; o < 1024; o <<= 1) {
        int t = (threadIdx.x >= o) ? sh[threadIdx.x - o] : 0;
        __syncthreads();
        sh[threadIdx.x] += t;
        __syncthreads();
    }
    if (i < n) g_rp[i] = sh[threadIdx.x] - v;   // exclusive
    if (threadIdx.x == 1023) g_blk[blockIdx.x] = sh[1023];
}
__global__ void k_scan2(int nb) {
    if (threadIdx.x == 0 && blockIdx.x == 0) {
        int run = 0;
        for (int b = 0; b < nb; b++) { int t = g_blk[b]; g_blk[b] = run; run += t; }
    }
}
__global__ void k_scan3(int n, int etot) {
    int i = blockIdx.x * blockDim.x + threadIdx.x;
    if (i < n) {
        int v = g_rp[i] + g_blk[i >> 10];
        g_rp[i] = v;
        g_pos[i] = v;
    }
    if (i == 0) g_rp[n] = etot;
}
__global__ void k_scatter(int etot) {
    int i = blockIdx.x * blockDim.x + threadIdx.x;
    if (i >= etot) return;
    int p = atomicAdd(&g_pos[g_dst[i]], 1);
    g_csrc[p] = g_src[i];
}

// ---------------- big fused GEMM  x @ [Wl | Wr] -> xl, xr ----------------------
// 128 threads, BM=128, BN=64, BK=16, 8x8 register tile, f32x2, double-buffered.
__global__ __launch_bounds__(128) void k_gemm1(
    const float* __restrict__ x, const float* __restrict__ Wl,
    const float* __restrict__ Wr, int n, int K)
{
    __shared__ float Xs[2][16][128];
    __shared__ float Ws[2][16][64];

    const int tid = threadIdx.x;
    const int tr = tid >> 3;        // 0..15
    const int tc = tid & 7;         // 0..7
    const int row0 = blockIdx.x * 128;
    const int my_r = tr * 8;        // 8 rows per thread
    const int my_c = tc * 8;        // 8 cols per thread

    unsigned long long acc[4][8];
#pragma unroll
    for (int i = 0; i < 4; i++)
#pragma unroll
        for (int j = 0; j < 8; j++) acc[i][j] = 0ull;

    // X load roles: 4 (row, kq) segments per thread
    const int xr0 = tid >> 2;             // +32*l
    const int xkq = (tid & 3) * 4;
    const float* xp[4];
#pragma unroll
    for (int l = 0; l < 4; l++) {
        int gr = row0 + xr0 + 32 * l;
        if (gr >= n) gr = n - 1;
        xp[l] = x + (size_t)gr * K + xkq;
    }

    // W load roles: 2 (k, col4) segments per thread
    const int wk0 = tid >> 4;             // +8*l
    const int wc4 = tid & 15;
    const float* wsrc = (wc4 < 8) ? Wl : Wr;
    const int wcc = (wc4 < 8) ? wc4 * 4 : (wc4 - 8) * 4;

    const int nch = (K + 15) >> 4;

    float xreg[4][4];
    float4 wreg[2];

    // ---- prefetch chunk 0
#pragma unroll
    for (int l = 0; l < 4; l++)
#pragma unroll
        for (int q = 0; q < 4; q++)
            xreg[l][q] = (xkq + q < K) ? xp[l][q] : 0.0f;
#pragma unroll
    for (int l = 0; l < 2; l++) {
        int gk = wk0 + 8 * l;
        wreg[l] = make_float4(0.f, 0.f, 0.f, 0.f);
        if (gk < K) wreg[l] = *(const float4*)(wsrc + (size_t)gk * HC + wcc);
    }

    // ---- store buf 0
#pragma unroll
    for (int l = 0; l < 4; l++)
#pragma unroll
        for (int q = 0; q < 4; q++)
            Xs[0][xkq + q][xr0 + 32 * l] = xreg[l][q];
#pragma unroll
    for (int l = 0; l < 2; l++)
        *(float4*)&Ws[0][wk0 + 8 * l][wc4 * 4] = wreg[l];
    __syncthreads();

    for (int c = 0; c < nch; c++) {
        const int buf = c & 1;
        const int k0n = (c + 1) * 16;
        const bool more = (c + 1 < nch);

        if (more) {
#pragma unroll
            for (int l = 0; l < 4; l++)
#pragma unroll
                for (int q = 0; q < 4; q++) {
                    int gk = k0n + xkq + q;
                    xreg[l][q] = (gk < K) ? xp[l][k0n + q] : 0.0f;
                }
#pragma unroll
            for (int l = 0; l < 2; l++) {
                int gk = k0n + wk0 + 8 * l;
                wreg[l] = make_float4(0.f, 0.f, 0.f, 0.f);
                if (gk < K) wreg[l] = *(const float4*)(wsrc + (size_t)gk * HC + wcc);
            }
        }

#pragma unroll
        for (int kk = 0; kk < 16; kk++) {
            ulonglong2 xa = *(const ulonglong2*)&Xs[buf][kk][my_r];
            ulonglong2 xb = *(const ulonglong2*)&Xs[buf][kk][my_r + 4];
            float4 wv0 = *(const float4*)&Ws[buf][kk][my_c];
            float4 wv1 = *(const float4*)&Ws[buf][kk][my_c + 4];
            unsigned long long w[8];
            w[0] = dup2(wv0.x); w[1] = dup2(wv0.y); w[2] = dup2(wv0.z); w[3] = dup2(wv0.w);
            w[4] = dup2(wv1.x); w[5] = dup2(wv1.y); w[6] = dup2(wv1.z); w[7] = dup2(wv1.w);
#pragma unroll
            for (int j = 0; j < 8; j++) {
                FMA2(acc[0][j], xa.x, w[j]);
                FMA2(acc[1][j], xa.y, w[j]);
                FMA2(acc[2][j], xb.x, w[j]);
                FMA2(acc[3][j], xb.y, w[j]);
            }
        }

        if (more) {
            const int nb = buf ^ 1;
#pragma unroll
            for (int l = 0; l < 4; l++)
#pragma unroll
                for (int q = 0; q < 4; q++)
                    Xs[nb][xkq + q][xr0 + 32 * l] = xreg[l][q];
#pragma unroll
            for (int l = 0; l < 2; l++)
                *(float4*)&Ws[nb][wk0 + 8 * l][wc4 * 4] = wreg[l];
        }
        __syncthreads();
    }

    // ---- store results (cols my_c..my_c+7 -> xl if tc<4 else xr)
    float* base = (tc < 4) ? g_xl : g_xr;
    const int cc = (tc < 4) ? my_c : (my_c - HC);
#pragma unroll
    for (int rp = 0; rp < 4; rp++) {
        float2 p[8];
#pragma unroll
        for (int j = 0; j < 8; j++) p[j] = unpack2(acc[rp][j]);
        int r_even = row0 + my_r + rp * 2;
        if (r_even < n) {
            float* o = base + (size_t)r_even * HC + cc;
            *(float4*)(o)     = make_float4(p[0].x, p[1].x, p[2].x, p[3].x);
            *(float4*)(o + 4) = make_float4(p[4].x, p[5].x, p[6].x, p[7].x);
        }
        int r_odd = r_even + 1;
        if (r_odd < n) {
            float* o = base + (size_t)r_odd * HC + cc;
            *(float4*)(o)     = make_float4(p[0].y, p[1].y, p[2].y, p[3].y);
            *(float4*)(o + 4) = make_float4(p[4].y, p[5].y, p[6].y, p[7].y);
        }
    }
}

// ---------------- per-node attention core (quad-edge, float4 lanes) ------------
__device__ __forceinline__ void attn_core(int node, int lane,
                                          const float* __restrict__ att,
                                          float4& accOut, float& ssumOut)
{
    const int c8 = lane & 7;
    const int eq = lane >> 3;
    const int beg = g_rp[node], end = g_rp[node + 1];
    const float4 xr4 = *(const float4*)(g_xr + (size_t)node * HC + c8 * 4);
    const float4 a4  = *(const float4*)(att + c8 * 4);
    float4 acc = make_float4(0.f, 0.f, 0.f, 0.f);
    float ssum = 0.f;

    for (int base = beg; base < end; base += 32) {
        int idx = base + lane;
        int sl = (idx < end) ? g_csrc[idx] : 0;
        int nsteps = min(32, end - base);
        for (int k4 = 0; k4 < nsteps; k4 += 4) {
            int sk = __shfl_sync(0xffffffffu, sl, k4 + eq);
            bool valid = (k4 + eq) < nsteps;
            float4 xl4 = __ldg((const float4*)(g_xl + (size_t)sk * HC) + c8);
            float z, p;
            z = xl4.x + xr4.x; z = fmaxf(z, 0.2f * z); p = z * a4.x;
            z = xl4.y + xr4.y; z = fmaxf(z, 0.2f * z); p = fmaf(z, a4.y, p);
            z = xl4.z + xr4.z; z = fmaxf(z, 0.2f * z); p = fmaf(z, a4.z, p);
            z = xl4.w + xr4.w; z = fmaxf(z, 0.2f * z); p = fmaf(z, a4.w, p);
            p += __shfl_xor_sync(0xffffffffu, p, 1);
            p += __shfl_xor_sync(0xffffffffu, p, 2);   // per-head score (within octet)
            float ex = valid ? __expf(p) : 0.0f;
            ssum += ex;
            acc.x = fmaf(ex, xl4.x, acc.x);
            acc.y = fmaf(ex, xl4.y, acc.y);
            acc.z = fmaf(ex, xl4.z, acc.z);
            acc.w = fmaf(ex, xl4.w, acc.w);
        }
    }
#pragma unroll
    for (int o = 8; o <= 16; o <<= 1) {
        acc.x += __shfl_xor_sync(0xffffffffu, acc.x, o);
        acc.y += __shfl_xor_sync(0xffffffffu, acc.y, o);
        acc.z += __shfl_xor_sync(0xffffffffu, acc.z, o);
        acc.w += __shfl_xor_sync(0xffffffffu, acc.w, o);
        ssum  += __shfl_xor_sync(0xffffffffu, ssum,  o);
    }
    accOut = acc;
    ssumOut = ssum;
}

// ---------------- layer 1: attention + bias + ELU -> g_h ------------------------
__global__ __launch_bounds__(256) void k_attn1(const float* __restrict__ att,
                                               const float* __restrict__ bias, int n)
{
    int w = (blockIdx.x * blockDim.x + threadIdx.x) >> 5;
    int lane = threadIdx.x & 31;
    if (w >= n) return;
    float4 acc; float ssum;
    attn_core(w, lane, att, acc, ssum);
    if (lane < 8) {
        float inv = 1.0f / (ssum + 1e-16f);
        float4 b4 = *(const float4*)(bias + lane * 4);
        float4 o;
        o.x = fmaf(acc.x, inv, b4.x); o.x = (o.x > 0.f) ? o.x : expm1f(o.x);
        o.y = fmaf(acc.y, inv, b4.y); o.y = (o.y > 0.f) ? o.y : expm1f(o.y);
        o.z = fmaf(acc.z, inv, b4.z); o.z = (o.z > 0.f) ? o.z : expm1f(o.z);
        o.w = fmaf(acc.w, inv, b4.w); o.w = (o.w > 0.f) ? o.w : expm1f(o.w);
        *(float4*)(g_h + (size_t)w * HC + lane * 4) = o;
    }
}

// ---------------- small GEMM  h @ [Wl2 | Wr2] (K=32) ----------------------------
__global__ __launch_bounds__(256) void k_gemm2(
    const float* __restrict__ Wl, const float* __restrict__ Wr, int n)
{
    __shared__ float Ws[32 * 64];
    __shared__ float hs[4][32];
    int tid = threadIdx.x;
#pragma unroll
    for (int l = 0; l < 8; l++) {
        int id = tid + l * 256;
        int k = id >> 6, c = id & 63;
        Ws[id] = (c < HC) ? Wl[k * HC + c] : Wr[k * HC + (c - HC)];
    }
    int node0 = blockIdx.x * 4;
    if (tid < 128) {
        int nn = node0 + (tid >> 5), k = tid & 31;
        hs[tid >> 5][k] = (nn < n) ? g_h[(size_t)nn * HC + k] : 0.0f;
    }
    __syncthreads();
    int ln = tid >> 6, c = tid & 63;
    int node = node0 + ln;
    if (node >= n) return;
    float acc = 0.0f;
#pragma unroll
    for (int k = 0; k < 32; k++) acc += hs[ln][k] * Ws[k * 64 + c];
    if (c < HC) g_xl[(size_t)node * HC + c] = acc;
    else        g_xr[(size_t)node * HC + (c - HC)] = acc;
}

// ---------------- layer 2: attention + ELU + FC + log_softmax -> out ------------
__global__ __launch_bounds__(256) void k_attn2(const float* __restrict__ att,
                                               const float* __restrict__ bias,
                                               const float* __restrict__ fcW,
                                               const float* __restrict__ fcb,
                                               float* __restrict__ out, int n)
{
    int w = (blockIdx.x * blockDim.x + threadIdx.x) >> 5;
    int lane = threadIdx.x & 31;
    if (w >= n) return;
    float4 acc; float ssum;
    attn_core(w, lane, att, acc, ssum);

    float4 h2 = make_float4(0.f, 0.f, 0.f, 0.f);
    if (lane < 8) {
        float inv = 1.0f / (ssum + 1e-16f);
        float4 b4 = *(const float4*)(bias + lane * 4);
        h2.x = fmaf(acc.x, inv, b4.x); h2.x = (h2.x > 0.f) ? h2.x : expm1f(h2.x);
        h2.y = fmaf(acc.y, inv, b4.y); h2.y = (h2.y > 0.f) ? h2.y : expm1f(h2.y);
        h2.z = fmaf(acc.z, inv, b4.z); h2.z = (h2.z > 0.f) ? h2.z : expm1f(h2.z);
        h2.w = fmaf(acc.w, inv, b4.w); h2.w = (h2.w > 0.f) ? h2.w : expm1f(h2.w);
    }

    float lg[7];
#pragma unroll
    for (int j = 0; j < 7; j++) {
        float p = 0.0f;
        if (lane < 8) {
            const float* wp = fcW + (lane * 4) * 7 + j;
            p = h2.x * wp[0] + h2.y * wp[7] + h2.z * wp[14] + h2.w * wp[21];
        }
        p += __shfl_xor_sync(0xffffffffu, p, 1);
        p += __shfl_xor_sync(0xffffffffu, p, 2);
        p += __shfl_xor_sync(0xffffffffu, p, 4);
        lg[j] = p;
    }
    if (lane == 0) {
        float mx = -1e30f;
#pragma unroll
        for (int j = 0; j < 7; j++) { lg[j] += fcb[j]; mx = fmaxf(mx, lg[j]); }
        float ss = 0.0f;
#pragma unroll
        for (int j = 0; j < 7; j++) ss += expf(lg[j] - mx);
        float lse = mx + logf(ss);
#pragma unroll
        for (int j = 0; j < 7; j++) out[(size_t)w * 7 + j] = lg[j] - lse;
    }
}

// ---------------- launch ---------------------------------------------------------
extern "C" void kernel_launch(void* const* d_in, const int* in_sizes, int n_in,
                              void* d_out, int out_size)
{
    const float* x    = (const float*)d_in[0];
    const void*  ei   = d_in[1];
    const float* Wl1  = (const float*)d_in[2];
    const float* Wr1  = (const float*)d_in[3];
    const float* a1   = (const float*)d_in[4];
    const float* b1   = (const float*)d_in[5];
    const float* Wl2  = (const float*)d_in[6];
    const float* Wr2  = (const float*)d_in[7];
    const float* a2   = (const float*)d_in[8];
    const float* b2   = (const float*)d_in[9];
    const float* fcW  = (const float*)d_in[10];
    const float* fcb  = (const float*)d_in[11];
    float*       out  = (float*)d_out;

    const int K = in_sizes[2] / HC;          // 1433
    const int n = in_sizes[0] / K;           // 100000
    const int E = in_sizes[1] / 2;           // 3200000
    const int etot = E + n;

    const int TB = 256;
    dim3 gEdge((etot + TB - 1) / TB);
    dim3 gN((n + TB - 1) / TB);
    int nWarpBlocks = (n * 32 + TB - 1) / TB;   // one warp per node
    int nb1024 = (n + 1023) / 1024;

    // --- decode + CSR build
    k_init0<<<gN, TB>>>(n);
    k_detect<<<(E + TB - 1) / TB, TB>>>((const int*)ei, E);
    k_prep_hist<<<gEdge, TB>>>(ei, E, n);
    k_scan1<<<nb1024, 1024>>>(n);
    k_scan2<<<1, 32>>>(nb1024);
    k_scan3<<<gN, TB>>>(n, etot);
    k_scatter<<<gEdge, TB>>>(etot);

    // --- layer 1
    k_gemm1<<<(n + 127) / 128, 128>>>(x, Wl1, Wr1, n, K);
    k_attn1<<<nWarpBlocks, TB>>>(a1, b1, n);

    // --- layer 2
    k_gemm2<<<(n + 3) / 4, 256>>>(Wl2, Wr2, n);
    k_attn2<<<nWarpBlocks, TB>>>(a2, b2, fcW, fcb, out, n);
}

// round 7
// speedup vs baseline: 1.1885x; 1.1885x over previous
#include <cuda_runtime.h>
#include <math.h>
#include <stdint.h>

// ---------------- problem constants ------------------------------------------
#define NMAX   100000
#define EMAX   3200000
#define ETOTMAX (EMAX + NMAX)
#define HC     32          // H*C

// ---------------- scratch (device globals: allocation-free rule) -------------
__device__ __align__(128) float g_xl [NMAX * HC];
__device__ __align__(128) float g_xr [NMAX * HC];
__device__ __align__(128) float g_h  [NMAX * HC];
__device__ __align__(128) int   g_src[ETOTMAX];
__device__ __align__(128) int   g_dst[ETOTMAX];
__device__ __align__(128) int   g_csrc[ETOTMAX];   // CSR: src ids sorted by dst
__device__ __align__(128) int   g_cnt[NMAX];
__device__ __align__(128) int   g_rp [NMAX + 1];   // CSR row pointers
__device__ __align__(128) int   g_pos[NMAX];       // scatter cursors
__device__ int g_i32flag;   // 1 if edge_index delivered as int32, 0 if int64

// ---------------- small helpers ------------------------------------------------
__device__ __forceinline__ uint32_t f2tf32(float f) {
    uint32_t r;
    asm("cvt.rna.tf32.f32 %0, %1;" : "=r"(r) : "f"(f));
    return r;
}
__device__ __forceinline__ void tf32split(float v, uint32_t& hi, uint32_t& lo) {
    hi = f2tf32(v);
    lo = f2tf32(v - __uint_as_float(hi));
}
#define MMA_TF32(c, a, b) \
    asm("mma.sync.aligned.m16n8k8.row.col.f32.tf32.tf32.f32 " \
        "{%0,%1,%2,%3}, {%4,%5,%6,%7}, {%8,%9}, {%0,%1,%2,%3};" \
        : "+f"((c)[0]), "+f"((c)[1]), "+f"((c)[2]), "+f"((c)[3]) \
        : "r"((a)[0]), "r"((a)[1]), "r"((a)[2]), "r"((a)[3]), \
          "r"((b)[0]), "r"((b)[1]))

// ---------------- init: zero histogram + reset dtype flag ---------------------
__global__ void k_init0(int n) {
    int i = blockIdx.x * blockDim.x + threadIdx.x;
    if (i < n) g_cnt[i] = 0;
    if (i == 0) g_i32flag = 0;
}

__global__ void k_detect(const int* __restrict__ w, int E) {
    long long i = (long long)blockIdx.x * blockDim.x + threadIdx.x;
    if (i >= E) return;
    if (w[2 * i + 1] != 0) g_i32flag = 1;     // benign race
}

// ---------------- edge decode + histogram (fused) ------------------------------
__global__ void k_prep_hist(const void* __restrict__ eiv, int E, int n) {
    int i = blockIdx.x * blockDim.x + threadIdx.x;
    int etot = E + n;
    if (i >= etot) return;
    int s, d;
    if (i < E) {
        if (g_i32flag) {
            const int* ei = (const int*)eiv;
            s = ei[i]; d = ei[(size_t)E + i];
        } else {
            const long long* ei = (const long long*)eiv;
            s = (int)ei[i]; d = (int)ei[(size_t)E + i];
        }
        s = min(max(s, 0), n - 1);
        d = min(max(d, 0), n - 1);
    } else {
        s = i - E; d = i - E;
    }
    g_src[i] = s;
    g_dst[i] = d;
    atomicAdd(&g_cnt[d], 1);
}

// ---------------- scan + scatter (counting sort by dst) ------------------------
__device__ __align__(128) int g_blk[128];
__global__ __launch_bounds__(1024) void k_scan1(int n) {
    __shared__ int sh[1024];
    int i = blockIdx.x * 1024 + threadIdx.x;
    int v = (i < n) ? g_cnt[i] : 0;
    sh[threadIdx.x] = v;
    __syncthreads();
#pragma unroll
    for (int o = 1; o < 1024; o <<= 1) {
        int t = (threadIdx.x >= o) ? sh[threadIdx.x - o] : 0;
        __syncthreads();
        sh[threadIdx.x] += t;
        __syncthreads();
    }
    if (i < n) g_rp[i] = sh[threadIdx.x] - v;   // exclusive
    if (threadIdx.x == 1023) g_blk[blockIdx.x] = sh[1023];
}
__global__ void k_scan2(int nb) {
    if (threadIdx.x == 0 && blockIdx.x == 0) {
        int run = 0;
        for (int b = 0; b < nb; b++) { int t = g_blk[b]; g_blk[b] = run; run += t; }
    }
}
__global__ void k_scan3(int n, int etot) {
    int i = blockIdx.x * blockDim.x + threadIdx.x;
    if (i < n) {
        int v = g_rp[i] + g_blk[i >> 10];
        g_rp[i] = v;
        g_pos[i] = v;
    }
    if (i == 0) g_rp[n] = etot;
}
__global__ void k_scatter(int etot) {
    int i = blockIdx.x * blockDim.x + threadIdx.x;
    if (i >= etot) return;
    int p = atomicAdd(&g_pos[g_dst[i]], 1);
    g_csrc[p] = g_src[i];
}

// ---------------- big fused GEMM  x @ [Wl | Wr] -> xl, xr  (TF32 tensor) -------
// 256 threads = 8 warps (4x2). BM=128, BN=64, BK=16. Warp tile 32x32.
// 3-term tf32 split (hi*hi + hi*lo + lo*hi) for fp32-grade accuracy.
#define XPAD 136
#define WPAD 72
__global__ __launch_bounds__(256) void k_gemm1(
    const float* __restrict__ x, const float* __restrict__ Wl,
    const float* __restrict__ Wr, int n, int K)
{
    __shared__ float Xs[2][16][XPAD];
    __shared__ float Ws[2][16][WPAD];

    const int tid = threadIdx.x;
    const int lane = tid & 31;
    const int warp = tid >> 5;
    const int gid = lane >> 2;        // 0..7
    const int tig = lane & 3;         // 0..3
    const int warp_row = warp & 3;    // 0..3  (32 rows each)
    const int warp_col = warp >> 2;   // 0..1  (32 cols each)
    const int r0w = warp_row * 32;
    const int wc0 = warp_col * 32;
    const int row0 = blockIdx.x * 128;

    float acc[2][4][4];
#pragma unroll
    for (int mt = 0; mt < 2; mt++)
#pragma unroll
        for (int nt = 0; nt < 4; nt++)
#pragma unroll
            for (int q = 0; q < 4; q++) acc[mt][nt][q] = 0.0f;

    // ---- loader roles (as R5): X: 2 segments, W: 1 segment --------------------
    const int xr1 = (tid + 0)   >> 2;       // 0..63
    const int xr2 = (tid + 256) >> 2;       // 64..127
    const int xkq = (tid & 3) * 4;
    int gr1 = row0 + xr1; if (gr1 >= n) gr1 = n - 1;
    int gr2 = row0 + xr2; if (gr2 >= n) gr2 = n - 1;
    const float* xp1 = x + (size_t)gr1 * K + xkq;
    const float* xp2 = x + (size_t)gr2 * K + xkq;

    const int wk = tid >> 4;                // 0..15
    const int wc4 = tid & 15;               // 4 cols each
    const float* wsrc = (wc4 < 8) ? Wl : Wr;
    const int wcc = (wc4 < 8) ? wc4 * 4 : (wc4 - 8) * 4;

    const int nch = (K + 15) >> 4;

    float xreg[2][4];
    float4 wreg;

    // ---- prefetch + store chunk 0
#pragma unroll
    for (int q = 0; q < 4; q++) {
        xreg[0][q] = (xkq + q < K) ? xp1[q] : 0.0f;
        xreg[1][q] = (xkq + q < K) ? xp2[q] : 0.0f;
    }
    wreg = make_float4(0.f, 0.f, 0.f, 0.f);
    if (wk < K) wreg = *(const float4*)(wsrc + (size_t)wk * HC + wcc);
#pragma unroll
    for (int q = 0; q < 4; q++) {
        Xs[0][xkq + q][xr1] = xreg[0][q];
        Xs[0][xkq + q][xr2] = xreg[1][q];
    }
    *(float4*)&Ws[0][wk][wc4 * 4] = wreg;
    __syncthreads();

    for (int c = 0; c < nch; c++) {
        const int buf = c & 1;
        const int k0n = (c + 1) * 16;
        const bool more = (c + 1 < nch);

        if (more) {
#pragma unroll
            for (int q = 0; q < 4; q++) {
                int gk = k0n + xkq + q;
                xreg[0][q] = (gk < K) ? xp1[k0n + q] : 0.0f;
                xreg[1][q] = (gk < K) ? xp2[k0n + q] : 0.0f;
            }
            wreg = make_float4(0.f, 0.f, 0.f, 0.f);
            int gk = k0n + wk;
            if (gk < K) wreg = *(const float4*)(wsrc + (size_t)gk * HC + wcc);
        }

        // ---- compute: 2 k-steps of 8
#pragma unroll
        for (int ks = 0; ks < 2; ks++) {
            const int kb = ks * 8;
            // B fragments for the 4 n-tiles
            uint32_t bh[4][2], bl[4][2];
#pragma unroll
            for (int nt = 0; nt < 4; nt++) {
                float b0 = Ws[buf][kb + tig][wc0 + nt * 8 + gid];
                float b1 = Ws[buf][kb + tig + 4][wc0 + nt * 8 + gid];
                tf32split(b0, bh[nt][0], bl[nt][0]);
                tf32split(b1, bh[nt][1], bl[nt][1]);
            }
#pragma unroll
            for (int mt = 0; mt < 2; mt++) {
                float a0 = Xs[buf][kb + tig][r0w + mt * 16 + gid];
                float a1 = Xs[buf][kb + tig][r0w + mt * 16 + gid + 8];
                float a2 = Xs[buf][kb + tig + 4][r0w + mt * 16 + gid];
                float a3 = Xs[buf][kb + tig + 4][r0w + mt * 16 + gid + 8];
                uint32_t ah[4], al[4];
                tf32split(a0, ah[0], al[0]);
                tf32split(a1, ah[1], al[1]);
                tf32split(a2, ah[2], al[2]);
                tf32split(a3, ah[3], al[3]);
#pragma unroll
                for (int nt = 0; nt < 4; nt++) {
                    MMA_TF32(acc[mt][nt], ah, bh[nt]);
                    MMA_TF32(acc[mt][nt], ah, bl[nt]);
                    MMA_TF32(acc[mt][nt], al, bh[nt]);
                }
            }
        }

        if (more) {
            const int nb = buf ^ 1;
#pragma unroll
            for (int q = 0; q < 4; q++) {
                Xs[nb][xkq + q][xr1] = xreg[0][q];
                Xs[nb][xkq + q][xr2] = xreg[1][q];
            }
            *(float4*)&Ws[nb][wk][wc4 * 4] = wreg;
        }
        __syncthreads();
    }

    // ---- store: warp_col 0 -> xl, 1 -> xr
    float* base = (warp_col == 0) ? g_xl : g_xr;
#pragma unroll
    for (int mt = 0; mt < 2; mt++) {
#pragma unroll
        for (int nt = 0; nt < 4; nt++) {
            int col = nt * 8 + tig * 2;
            int r = row0 + r0w + mt * 16 + gid;
            if (r < n)
                *(float2*)&base[(size_t)r * HC + col] =
                    make_float2(acc[mt][nt][0], acc[mt][nt][1]);
            int r2 = r + 8;
            if (r2 < n)
                *(float2*)&base[(size_t)r2 * HC + col] =
                    make_float2(acc[mt][nt][2], acc[mt][nt][3]);
        }
    }
}

// ---------------- per-node attention core (quad-edge, float4 lanes) ------------
__device__ __forceinline__ void attn_core(int node, int lane,
                                          const float* __restrict__ att,
                                          float4& accOut, float& ssumOut)
{
    const int c8 = lane & 7;
    const int eq = lane >> 3;
    const int beg = g_rp[node], end = g_rp[node + 1];
    const float4 xr4 = *(const float4*)(g_xr + (size_t)node * HC + c8 * 4);
    const float4 a4  = *(const float4*)(att + c8 * 4);
    float4 acc = make_float4(0.f, 0.f, 0.f, 0.f);
    float ssum = 0.f;

    for (int base = beg; base < end; base += 32) {
        int idx = base + lane;
        int sl = (idx < end) ? g_csrc[idx] : 0;
        int nsteps = min(32, end - base);
        for (int k4 = 0; k4 < nsteps; k4 += 4) {
            int sk = __shfl_sync(0xffffffffu, sl, k4 + eq);
            bool valid = (k4 + eq) < nsteps;
            float4 xl4 = __ldg((const float4*)(g_xl + (size_t)sk * HC) + c8);
            float z, p;
            z = xl4.x + xr4.x; z = fmaxf(z, 0.2f * z); p = z * a4.x;
            z = xl4.y + xr4.y; z = fmaxf(z, 0.2f * z); p = fmaf(z, a4.y, p);
            z = xl4.z + xr4.z; z = fmaxf(z, 0.2f * z); p = fmaf(z, a4.z, p);
            z = xl4.w + xr4.w; z = fmaxf(z, 0.2f * z); p = fmaf(z, a4.w, p);
            p += __shfl_xor_sync(0xffffffffu, p, 1);
            p += __shfl_xor_sync(0xffffffffu, p, 2);   // per-head score (within octet)
            float ex = valid ? __expf(p) : 0.0f;
            ssum += ex;
            acc.x = fmaf(ex, xl4.x, acc.x);
            acc.y = fmaf(ex, xl4.y, acc.y);
            acc.z = fmaf(ex, xl4.z, acc.z);
            acc.w = fmaf(ex, xl4.w, acc.w);
        }
    }
#pragma unroll
    for (int o = 8; o <= 16; o <<= 1) {
        acc.x += __shfl_xor_sync(0xffffffffu, acc.x, o);
        acc.y += __shfl_xor_sync(0xffffffffu, acc.y, o);
        acc.z += __shfl_xor_sync(0xffffffffu, acc.z, o);
        acc.w += __shfl_xor_sync(0xffffffffu, acc.w, o);
        ssum  += __shfl_xor_sync(0xffffffffu, ssum,  o);
    }
    accOut = acc;
    ssumOut = ssum;
}

// ---------------- layer 1: attention + bias + ELU -> g_h ------------------------
__global__ __launch_bounds__(256) void k_attn1(const float* __restrict__ att,
                                               const float* __restrict__ bias, int n)
{
    int w = (blockIdx.x * blockDim.x + threadIdx.x) >> 5;
    int lane = threadIdx.x & 31;
    if (w >= n) return;
    float4 acc; float ssum;
    attn_core(w, lane, att, acc, ssum);
    if (lane < 8) {
        float inv = 1.0f / (ssum + 1e-16f);
        float4 b4 = *(const float4*)(bias + lane * 4);
        float4 o;
        o.x = fmaf(acc.x, inv, b4.x); o.x = (o.x > 0.f) ? o.x : expm1f(o.x);
        o.y = fmaf(acc.y, inv, b4.y); o.y = (o.y > 0.f) ? o.y : expm1f(o.y);
        o.z = fmaf(acc.z, inv, b4.z); o.z = (o.z > 0.f) ? o.z : expm1f(o.z);
        o.w = fmaf(acc.w, inv, b4.w); o.w = (o.w > 0.f) ? o.w : expm1f(o.w);
        *(float4*)(g_h + (size_t)w * HC + lane * 4) = o;
    }
}

// ---------------- small GEMM  h @ [Wl2 | Wr2] (K=32) ----------------------------
__global__ __launch_bounds__(256) void k_gemm2(
    const float* __restrict__ Wl, const float* __restrict__ Wr, int n)
{
    __shared__ float Ws2[32 * 64];
    __shared__ float hs[4][32];
    int tid = threadIdx.x;
#pragma unroll
    for (int l = 0; l < 8; l++) {
        int id = tid + l * 256;
        int k = id >> 6, c = id & 63;
        Ws2[id] = (c < HC) ? Wl[k * HC + c] : Wr[k * HC + (c - HC)];
    }
    int node0 = blockIdx.x * 4;
    if (tid < 128) {
        int nn = node0 + (tid >> 5), k = tid & 31;
        hs[tid >> 5][k] = (nn < n) ? g_h[(size_t)nn * HC + k] : 0.0f;
    }
    __syncthreads();
    int ln = tid >> 6, c = tid & 63;
    int node = node0 + ln;
    if (node >= n) return;
    float acc = 0.0f;
#pragma unroll
    for (int k = 0; k < 32; k++) acc += hs[ln][k] * Ws2[k * 64 + c];
    if (c < HC) g_xl[(size_t)node * HC + c] = acc;
    else        g_xr[(size_t)node * HC + (c - HC)] = acc;
}

// ---------------- layer 2: attention + ELU + FC + log_softmax -> out ------------
__global__ __launch_bounds__(256) void k_attn2(const float* __restrict__ att,
                                               const float* __restrict__ bias,
                                               const float* __restrict__ fcW,
                                               const float* __restrict__ fcb,
                                               float* __restrict__ out, int n)
{
    int w = (blockIdx.x * blockDim.x + threadIdx.x) >> 5;
    int lane = threadIdx.x & 31;
    if (w >= n) return;
    float4 acc; float ssum;
    attn_core(w, lane, att, acc, ssum);

    float4 h2 = make_float4(0.f, 0.f, 0.f, 0.f);
    if (lane < 8) {
        float inv = 1.0f / (ssum + 1e-16f);
        float4 b4 = *(const float4*)(bias + lane * 4);
        h2.x = fmaf(acc.x, inv, b4.x); h2.x = (h2.x > 0.f) ? h2.x : expm1f(h2.x);
        h2.y = fmaf(acc.y, inv, b4.y); h2.y = (h2.y > 0.f) ? h2.y : expm1f(h2.y);
        h2.z = fmaf(acc.z, inv, b4.z); h2.z = (h2.z > 0.f) ? h2.z : expm1f(h2.z);
        h2.w = fmaf(acc.w, inv, b4.w); h2.w = (h2.w > 0.f) ? h2.w : expm1f(h2.w);
    }

    float lg[7];
#pragma unroll
    for (int j = 0; j < 7; j++) {
        float p = 0.0f;
        if (lane < 8) {
            const float* wp = fcW + (lane * 4) * 7 + j;
            p = h2.x * wp[0] + h2.y * wp[7] + h2.z * wp[14] + h2.w * wp[21];
        }
        p += __shfl_xor_sync(0xffffffffu, p, 1);
        p += __shfl_xor_sync(0xffffffffu, p, 2);
        p += __shfl_xor_sync(0xffffffffu, p, 4);
        lg[j] = p;
    }
    if (lane == 0) {
        float mx = -1e30f;
#pragma unroll
        for (int j = 0; j < 7; j++) { lg[j] += fcb[j]; mx = fmaxf(mx, lg[j]); }
        float ss = 0.0f;
#pragma unroll
        for (int j = 0; j < 7; j++) ss += expf(lg[j] - mx);
        float lse = mx + logf(ss);
#pragma unroll
        for (int j = 0; j < 7; j++) out[(size_t)w * 7 + j] = lg[j] - lse;
    }
}

// ---------------- launch ---------------------------------------------------------
extern "C" void kernel_launch(void* const* d_in, const int* in_sizes, int n_in,
                              void* d_out, int out_size)
{
    const float* x    = (const float*)d_in[0];
    const void*  ei   = d_in[1];
    const float* Wl1  = (const float*)d_in[2];
    const float* Wr1  = (const float*)d_in[3];
    const float* a1   = (const float*)d_in[4];
    const float* b1   = (const float*)d_in[5];
    const float* Wl2  = (const float*)d_in[6];
    const float* Wr2  = (const float*)d_in[7];
    const float* a2   = (const float*)d_in[8];
    const float* b2   = (const float*)d_in[9];
    const float* fcW  = (const float*)d_in[10];
    const float* fcb  = (const float*)d_in[11];
    float*       out  = (float*)d_out;

    const int K = in_sizes[2] / HC;          // 1433
    const int n = in_sizes[0] / K;           // 100000
    const int E = in_sizes[1] / 2;           // 3200000
    const int etot = E + n;

    const int TB = 256;
    dim3 gEdge((etot + TB - 1) / TB);
    dim3 gN((n + TB - 1) / TB);
    int nWarpBlocks = (n * 32 + TB - 1) / TB;   // one warp per node
    int nb1024 = (n + 1023) / 1024;

    // --- decode + CSR build
    k_init0<<<gN, TB>>>(n);
    k_detect<<<(E + TB - 1) / TB, TB>>>((const int*)ei, E);
    k_prep_hist<<<gEdge, TB>>>(ei, E, n);
    k_scan1<<<nb1024, 1024>>>(n);
    k_scan2<<<1, 32>>>(nb1024);
    k_scan3<<<gN, TB>>>(n, etot);
    k_scatter<<<gEdge, TB>>>(etot);

    // --- layer 1
    k_gemm1<<<(n + 127) / 128, 256>>>(x, Wl1, Wr1, n, K);
    k_attn1<<<nWarpBlocks, TB>>>(a1, b1, n);

    // --- layer 2
    k_gemm2<<<(n + 3) / 4, 256>>>(Wl2, Wr2, n);
    k_attn2<<<nWarpBlocks, TB>>>(a2, b2, fcW, fcb, out, n);
}